// round 8
// baseline (speedup 1.0000x reference)
#include <cuda_runtime.h>
#include <cstdint>

#define HIDDEN 128
#define MAX_NODES 40000

// Scratch: per-node dot products with the two halves of att_w.
// (device globals — no dynamic allocation allowed by the harness)
__device__ float g_s1[MAX_NODES];
__device__ float g_s2[MAX_NODES];

// ---------------------------------------------------------------------------
// Kernel 1: per-node s1[n] = x[n] . w[0:128], s2[n] = x[n] . w[128:256]
// One warp per node; lane k handles floats [4k, 4k+4).
// ---------------------------------------------------------------------------
__global__ void node_dots_kernel(const float* __restrict__ x,
                                 const float* __restrict__ att_w,
                                 int n_nodes) {
    int gtid = blockIdx.x * blockDim.x + threadIdx.x;
    int node = gtid >> 5;
    int lane = threadIdx.x & 31;
    if (node >= n_nodes) return;

    const float4 xv = reinterpret_cast<const float4*>(x + (size_t)node * HIDDEN)[lane];
    const float4 w1 = reinterpret_cast<const float4*>(att_w)[lane];        // w[0:128]
    const float4 w2 = reinterpret_cast<const float4*>(att_w)[32 + lane];   // w[128:256]

    float p1 = xv.x * w1.x + xv.y * w1.y + xv.z * w1.z + xv.w * w1.w;
    float p2 = xv.x * w2.x + xv.y * w2.y + xv.z * w2.z + xv.w * w2.w;

    #pragma unroll
    for (int off = 16; off > 0; off >>= 1) {
        p1 += __shfl_xor_sync(0xFFFFFFFFu, p1, off);
        p2 += __shfl_xor_sync(0xFFFFFFFFu, p2, off);
    }
    if (lane == 0) {
        g_s1[node] = p1;
        g_s2[node] = p2;
    }
}

// ---------------------------------------------------------------------------
// Kernel 2: out = eps * x   (output buffer is poisoned; must initialize)
// ---------------------------------------------------------------------------
__global__ void init_out_kernel(const float* __restrict__ x,
                                const float* __restrict__ eps,
                                float* __restrict__ out,
                                int n_f4) {
    float e = eps[0];
    int stride = gridDim.x * blockDim.x;
    const float4* x4 = reinterpret_cast<const float4*>(x);
    float4* o4 = reinterpret_cast<float4*>(out);
    for (int i = blockIdx.x * blockDim.x + threadIdx.x; i < n_f4; i += stride) {
        float4 v = x4[i];
        v.x *= e; v.y *= e; v.z *= e; v.w *= e;
        o4[i] = v;
    }
}

// ---------------------------------------------------------------------------
// Kernel 3: per-edge scatter.
// One warp per edge. alpha = (1-eps)*tanh(s1[row] + s2[col] + b).
// lane k: out[col][4k:4k+4] += alpha * x[row][4k:4k+4] via red.global.add.v4.f32
// edge_index is int32 (JAX default config downcasts int64 -> int32).
// ---------------------------------------------------------------------------
__global__ void edge_kernel(const float* __restrict__ x,
                            const int* __restrict__ edge_index,
                            const float* __restrict__ att_b,
                            const float* __restrict__ eps,
                            float* __restrict__ out,
                            int n_edges) {
    int gtid = blockIdx.x * blockDim.x + threadIdx.x;
    int e = gtid >> 5;
    int lane = threadIdx.x & 31;
    if (e >= n_edges) return;

    // Broadcast loads (all lanes same address -> single transaction)
    int row = __ldg(&edge_index[e]);
    int col = __ldg(&edge_index[n_edges + e]);

    float b = __ldg(&att_b[0]);
    float one_m_eps = 1.0f - __ldg(&eps[0]);

    float logit = g_s1[row] + g_s2[col] + b;
    float alpha = one_m_eps * tanhf(logit);

    const float4 xi = reinterpret_cast<const float4*>(x + (size_t)row * HIDDEN)[lane];
    float4 m;
    m.x = alpha * xi.x;
    m.y = alpha * xi.y;
    m.z = alpha * xi.z;
    m.w = alpha * xi.w;

    float* dst = out + (size_t)col * HIDDEN + lane * 4;
    asm volatile("red.global.add.v4.f32 [%0], {%1, %2, %3, %4};"
                 :: "l"(dst), "f"(m.x), "f"(m.y), "f"(m.z), "f"(m.w)
                 : "memory");
}

// ---------------------------------------------------------------------------
// Launch
// ---------------------------------------------------------------------------
extern "C" void kernel_launch(void* const* d_in, const int* in_sizes, int n_in,
                              void* d_out, int out_size) {
    const float* x     = (const float*)d_in[0];   // [N, 128] f32
    const int*   ei    = (const int*)d_in[1];     // [2, E] int32 (JAX x64 disabled)
    const float* att_w = (const float*)d_in[2];   // [1, 256]
    const float* att_b = (const float*)d_in[3];   // [1]
    const float* eps   = (const float*)d_in[4];   // [1]
    float*       out   = (float*)d_out;           // [N, 128]

    const int n_nodes = in_sizes[0] / HIDDEN;
    const int n_edges = in_sizes[1] / 2;

    // Kernel 1: per-node dot products. One warp/node, 8 warps/block.
    {
        int threads = 256;
        int blocks = (n_nodes * 32 + threads - 1) / threads;
        node_dots_kernel<<<blocks, threads>>>(x, att_w, n_nodes);
    }

    // Kernel 2: out = eps * x
    {
        int n_f4 = out_size / 4;
        int threads = 256;
        int blocks = 1184;  // ~8 blocks/SM grid-stride
        init_out_kernel<<<blocks, threads>>>(x, eps, out, n_f4);
    }

    // Kernel 3: edge scatter. One warp/edge, 8 warps/block.
    {
        int threads = 256;
        int blocks = (n_edges * 32 + threads - 1) / threads;  // 80000 for E=640k
        edge_kernel<<<blocks, threads>>>(x, ei, att_b, eps, out, n_edges);
    }
}

// round 9
// speedup vs baseline: 1.2924x; 1.2924x over previous
#include <cuda_runtime.h>
#include <cstdint>

#define HIDDEN    128
#define MAX_NODES 40000
#define MAX_EDGES 640000
#define SCAN_BLK  1024

// Scratch (device globals — no dynamic allocation allowed)
__device__ float    g_s1[MAX_NODES];
__device__ float    g_s2[MAX_NODES];
__device__ unsigned g_deg[MAX_NODES];          // degree histogram (by col)
__device__ unsigned g_part[MAX_NODES];         // block-local exclusive scan
__device__ unsigned g_bsum[64];                // per-block sums
__device__ unsigned g_bsum_sc[64];             // scanned block sums
__device__ int      g_off[MAX_NODES + 1];      // CSR offsets (by col)
__device__ unsigned g_cur[MAX_NODES];          // running cursors for scatter
__device__ int2     g_pairs[MAX_EDGES];        // {row, alpha-bits} sorted by col

// ---------------------------------------------------------------------------
// K1: per-node s1/s2 dot products + zero the degree histogram.
// One warp per node; lane k handles floats [4k, 4k+4).
// ---------------------------------------------------------------------------
__global__ void node_dots_kernel(const float* __restrict__ x,
                                 const float* __restrict__ att_w,
                                 int n_nodes) {
    int gtid = blockIdx.x * blockDim.x + threadIdx.x;
    if (gtid < n_nodes) g_deg[gtid] = 0u;

    int node = gtid >> 5;
    int lane = threadIdx.x & 31;
    if (node >= n_nodes) return;

    const float4 xv = reinterpret_cast<const float4*>(x + (size_t)node * HIDDEN)[lane];
    const float4 w1 = reinterpret_cast<const float4*>(att_w)[lane];
    const float4 w2 = reinterpret_cast<const float4*>(att_w)[32 + lane];

    float p1 = xv.x * w1.x + xv.y * w1.y + xv.z * w1.z + xv.w * w1.w;
    float p2 = xv.x * w2.x + xv.y * w2.y + xv.z * w2.z + xv.w * w2.w;

    #pragma unroll
    for (int off = 16; off > 0; off >>= 1) {
        p1 += __shfl_xor_sync(0xFFFFFFFFu, p1, off);
        p2 += __shfl_xor_sync(0xFFFFFFFFu, p2, off);
    }
    if (lane == 0) {
        g_s1[node] = p1;
        g_s2[node] = p2;
    }
}

// ---------------------------------------------------------------------------
// K2: degree histogram over col (no-return atomic -> RED).
// ---------------------------------------------------------------------------
__global__ void hist_kernel(const int* __restrict__ edge_index, int n_edges) {
    int e = blockIdx.x * blockDim.x + threadIdx.x;
    if (e >= n_edges) return;
    int col = __ldg(&edge_index[n_edges + e]);
    atomicAdd(&g_deg[col], 1u);
}

// ---------------------------------------------------------------------------
// K3a: per-block exclusive scan of g_deg (block = 1024 elems).
// ---------------------------------------------------------------------------
__global__ void scan1_kernel(int n) {
    __shared__ unsigned s[SCAN_BLK];
    int i = blockIdx.x * SCAN_BLK + threadIdx.x;
    unsigned v = (i < n) ? g_deg[i] : 0u;
    s[threadIdx.x] = v;
    __syncthreads();
    #pragma unroll
    for (int off = 1; off < SCAN_BLK; off <<= 1) {
        unsigned t = (threadIdx.x >= off) ? s[threadIdx.x - off] : 0u;
        __syncthreads();
        s[threadIdx.x] += t;
        __syncthreads();
    }
    unsigned incl = s[threadIdx.x];
    if (i < n) g_part[i] = incl - v;                 // exclusive within block
    if (threadIdx.x == SCAN_BLK - 1) g_bsum[blockIdx.x] = incl;
}

// K3b: scan the (<=64) block sums. Single block.
__global__ void scan2_kernel(int nb) {
    __shared__ unsigned s[64];
    unsigned v = (threadIdx.x < (unsigned)nb) ? g_bsum[threadIdx.x] : 0u;
    s[threadIdx.x] = v;
    __syncthreads();
    #pragma unroll
    for (int off = 1; off < 64; off <<= 1) {
        unsigned t = (threadIdx.x >= (unsigned)off) ? s[threadIdx.x - off] : 0u;
        __syncthreads();
        s[threadIdx.x] += t;
        __syncthreads();
    }
    if (threadIdx.x < (unsigned)nb) g_bsum_sc[threadIdx.x] = s[threadIdx.x] - v;
}

// K3c: finalize offsets + cursors.
__global__ void scan3_kernel(int n, int n_edges) {
    int i = blockIdx.x * SCAN_BLK + threadIdx.x;
    if (i < n) {
        int o = (int)(g_part[i] + g_bsum_sc[blockIdx.x]);
        g_off[i] = o;
        g_cur[i] = (unsigned)o;
    }
    if (i == 0) g_off[n] = n_edges;
}

// ---------------------------------------------------------------------------
// K4: per-edge alpha + scatter {row, alpha} into col-sorted pair array.
// alpha folds in (1 - eps).
// ---------------------------------------------------------------------------
__global__ void alpha_scatter_kernel(const int* __restrict__ edge_index,
                                     const float* __restrict__ att_b,
                                     const float* __restrict__ eps,
                                     int n_edges) {
    int e = blockIdx.x * blockDim.x + threadIdx.x;
    if (e >= n_edges) return;
    int row = __ldg(&edge_index[e]);
    int col = __ldg(&edge_index[n_edges + e]);
    float a = (1.0f - __ldg(&eps[0])) * tanhf(g_s1[row] + g_s2[col] + __ldg(&att_b[0]));
    unsigned p = atomicAdd(&g_cur[col], 1u);
    g_pairs[p] = make_int2(row, __float_as_int(a));
}

// ---------------------------------------------------------------------------
// K5: gather. One warp per destination node.
// out[c] = eps*x[c] + sum_e alpha_e * x[row_e]   (alpha already *(1-eps))
// ---------------------------------------------------------------------------
__global__ void gather_kernel(const float* __restrict__ x,
                              const float* __restrict__ eps,
                              float* __restrict__ out,
                              int n_nodes) {
    int gtid = blockIdx.x * blockDim.x + threadIdx.x;
    int node = gtid >> 5;
    int lane = threadIdx.x & 31;
    if (node >= n_nodes) return;

    int beg = g_off[node];
    int end = g_off[node + 1];
    const float4* x4 = reinterpret_cast<const float4*>(x);

    float4 acc = make_float4(0.f, 0.f, 0.f, 0.f);

    int i = beg;
    // 4x unrolled: batch pair loads, then batch x gathers -> MLP ~8
    for (; i + 4 <= end; i += 4) {
        int2 p0 = __ldg(&g_pairs[i]);
        int2 p1 = __ldg(&g_pairs[i + 1]);
        int2 p2 = __ldg(&g_pairs[i + 2]);
        int2 p3 = __ldg(&g_pairs[i + 3]);
        float4 v0 = __ldg(&x4[(size_t)p0.x * 32 + lane]);
        float4 v1 = __ldg(&x4[(size_t)p1.x * 32 + lane]);
        float4 v2 = __ldg(&x4[(size_t)p2.x * 32 + lane]);
        float4 v3 = __ldg(&x4[(size_t)p3.x * 32 + lane]);
        float a0 = __int_as_float(p0.y), a1 = __int_as_float(p1.y);
        float a2 = __int_as_float(p2.y), a3 = __int_as_float(p3.y);
        acc.x += a0 * v0.x + a1 * v1.x + a2 * v2.x + a3 * v3.x;
        acc.y += a0 * v0.y + a1 * v1.y + a2 * v2.y + a3 * v3.y;
        acc.z += a0 * v0.z + a1 * v1.z + a2 * v2.z + a3 * v3.z;
        acc.w += a0 * v0.w + a1 * v1.w + a2 * v2.w + a3 * v3.w;
    }
    for (; i < end; ++i) {
        int2 p = __ldg(&g_pairs[i]);
        float4 v = __ldg(&x4[(size_t)p.x * 32 + lane]);
        float a = __int_as_float(p.y);
        acc.x += a * v.x; acc.y += a * v.y; acc.z += a * v.z; acc.w += a * v.w;
    }

    float e = __ldg(&eps[0]);
    float4 xc = __ldg(&x4[(size_t)node * 32 + lane]);
    float4 o;
    o.x = e * xc.x + acc.x;
    o.y = e * xc.y + acc.y;
    o.z = e * xc.z + acc.z;
    o.w = e * xc.w + acc.w;
    reinterpret_cast<float4*>(out)[(size_t)node * 32 + lane] = o;
}

// ---------------------------------------------------------------------------
// Launch
// ---------------------------------------------------------------------------
extern "C" void kernel_launch(void* const* d_in, const int* in_sizes, int n_in,
                              void* d_out, int out_size) {
    const float* x     = (const float*)d_in[0];   // [N, 128] f32
    const int*   ei    = (const int*)d_in[1];     // [2, E] int32
    const float* att_w = (const float*)d_in[2];   // [1, 256]
    const float* att_b = (const float*)d_in[3];   // [1]
    const float* eps   = (const float*)d_in[4];   // [1]
    float*       out   = (float*)d_out;           // [N, 128]

    const int n_nodes = in_sizes[0] / HIDDEN;
    const int n_edges = in_sizes[1] / 2;
    const int nb_scan = (n_nodes + SCAN_BLK - 1) / SCAN_BLK;

    // K1: node dots + zero histogram (one warp/node)
    {
        int blocks = (n_nodes * 32 + 255) / 256;
        node_dots_kernel<<<blocks, 256>>>(x, att_w, n_nodes);
    }
    // K2: histogram by col
    hist_kernel<<<(n_edges + 255) / 256, 256>>>(ei, n_edges);

    // K3: exclusive scan -> offsets + cursors
    scan1_kernel<<<nb_scan, SCAN_BLK>>>(n_nodes);
    scan2_kernel<<<1, 64>>>(nb_scan);
    scan3_kernel<<<nb_scan, SCAN_BLK>>>(n_nodes, n_edges);

    // K4: alpha + scatter into CSR bins
    alpha_scatter_kernel<<<(n_edges + 255) / 256, 256>>>(ei, att_b, eps, n_edges);

    // K5: gather (one warp/node), init fused
    {
        int blocks = (n_nodes * 32 + 255) / 256;
        gather_kernel<<<blocks, 256>>>(x, eps, out, n_nodes);
    }
}

// round 11
// speedup vs baseline: 1.3873x; 1.0734x over previous
#include <cuda_runtime.h>
#include <cstdint>

#define HIDDEN    128
#define MAX_NODES 40000
#define MAX_EDGES 640000
#define SCAN_BLK  1024

// Scratch (device globals — zero-initialized at module load; no dynamic alloc)
__device__ float    g_s1[MAX_NODES];
__device__ float    g_s2[MAX_NODES];
__device__ unsigned g_deg[MAX_NODES];      // degree histogram (by col); ALWAYS left
                                           // zeroed by gather_kernel's tail so each
                                           // call starts from zero (first call: .bss)
__device__ unsigned g_part[MAX_NODES];     // block-local exclusive scan
__device__ unsigned g_bsum[64];            // per-scan-block sums
__device__ int      g_off[MAX_NODES + 1];  // CSR offsets (by col)
__device__ unsigned g_cur[MAX_NODES];      // running cursors for scatter
__device__ int2     g_pairs[MAX_EDGES];    // {row, alpha-bits} grouped by col

// ---------------------------------------------------------------------------
// K1: fused per-node dot products (4 nodes per warp, ILP'd shfl ladders)
//     + edge histogram by col (grid-stride tail; g_deg pre-zeroed).
// ---------------------------------------------------------------------------
__global__ void dots_hist_kernel(const float* __restrict__ x,
                                 const float* __restrict__ att_w,
                                 const int* __restrict__ edge_index,
                                 int n_nodes, int n_edges) {
    int tid  = blockIdx.x * blockDim.x + threadIdx.x;
    int warp = tid >> 5;
    int lane = threadIdx.x & 31;
    int n0 = warp * 4;

    if (n0 < n_nodes) {
        const float4 w1 = reinterpret_cast<const float4*>(att_w)[lane];
        const float4 w2 = reinterpret_cast<const float4*>(att_w)[32 + lane];
        const float4* x4 = reinterpret_cast<const float4*>(x);

        float p1[4], p2[4];
        #pragma unroll
        for (int j = 0; j < 4; ++j) {
            int n = n0 + j;
            float4 xv = (n < n_nodes) ? __ldg(&x4[(size_t)n * 32 + lane])
                                      : make_float4(0.f, 0.f, 0.f, 0.f);
            p1[j] = xv.x * w1.x + xv.y * w1.y + xv.z * w1.z + xv.w * w1.w;
            p2[j] = xv.x * w2.x + xv.y * w2.y + xv.z * w2.z + xv.w * w2.w;
        }
        #pragma unroll
        for (int off = 16; off > 0; off >>= 1) {
            #pragma unroll
            for (int j = 0; j < 4; ++j) {
                p1[j] += __shfl_xor_sync(0xFFFFFFFFu, p1[j], off);
                p2[j] += __shfl_xor_sync(0xFFFFFFFFu, p2[j], off);
            }
        }
        if (lane == 0) {
            #pragma unroll
            for (int j = 0; j < 4; ++j) {
                int n = n0 + j;
                if (n < n_nodes) { g_s1[n] = p1[j]; g_s2[n] = p2[j]; }
            }
        }
    }

    // Histogram (independent of the dots; g_deg is zero on entry)
    int stride = gridDim.x * blockDim.x;
    for (int e = tid; e < n_edges; e += stride) {
        int col = __ldg(&edge_index[n_edges + e]);
        atomicAdd(&g_deg[col], 1u);
    }
}

// ---------------------------------------------------------------------------
// K2: block-level exclusive scan of g_deg (1024/block), shfl-based.
// ---------------------------------------------------------------------------
__global__ void scan1_kernel(int n) {
    __shared__ unsigned wsum[32];
    int i = blockIdx.x * SCAN_BLK + threadIdx.x;
    int lane = threadIdx.x & 31;
    int wid  = threadIdx.x >> 5;

    unsigned v = (i < n) ? g_deg[i] : 0u;
    unsigned incl = v;
    #pragma unroll
    for (int off = 1; off < 32; off <<= 1) {
        unsigned t = __shfl_up_sync(0xFFFFFFFFu, incl, off);
        if (lane >= off) incl += t;
    }
    if (lane == 31) wsum[wid] = incl;
    __syncthreads();
    if (wid == 0) {
        unsigned ws = wsum[lane];
        #pragma unroll
        for (int off = 1; off < 32; off <<= 1) {
            unsigned t = __shfl_up_sync(0xFFFFFFFFu, ws, off);
            if (lane >= off) ws += t;
        }
        wsum[lane] = ws;   // inclusive warp-sum scan
    }
    __syncthreads();
    unsigned woff = wid ? wsum[wid - 1] : 0u;
    if (i < n) g_part[i] = woff + incl - v;
    if (threadIdx.x == SCAN_BLK - 1) g_bsum[blockIdx.x] = woff + incl;
}

// ---------------------------------------------------------------------------
// K3: finalize offsets: each block warp-reduces its prefix of g_bsum.
// ---------------------------------------------------------------------------
__global__ void scan_fin_kernel(int n, int n_edges) {
    __shared__ unsigned s_pre;
    if (threadIdx.x < 32) {
        unsigned a = 0;
        int i0 = threadIdx.x, i1 = threadIdx.x + 32;
        if (i0 < (int)blockIdx.x) a += g_bsum[i0];
        if (i1 < (int)blockIdx.x) a += g_bsum[i1];
        #pragma unroll
        for (int off = 16; off > 0; off >>= 1)
            a += __shfl_xor_sync(0xFFFFFFFFu, a, off);
        if (threadIdx.x == 0) s_pre = a;
    }
    __syncthreads();
    unsigned pre = s_pre;
    int i = blockIdx.x * SCAN_BLK + threadIdx.x;
    if (i < n) {
        int o = (int)(g_part[i] + pre);
        g_off[i] = o;
        g_cur[i] = (unsigned)o;
    }
    if (i == 0) g_off[n] = n_edges;
}

// ---------------------------------------------------------------------------
// K4: per-edge alpha (folds in 1-eps) + scatter {row, alpha} into col bins.
// ---------------------------------------------------------------------------
__global__ void alpha_scatter_kernel(const int* __restrict__ edge_index,
                                     const float* __restrict__ att_b,
                                     const float* __restrict__ eps,
                                     int n_edges) {
    int e = blockIdx.x * blockDim.x + threadIdx.x;
    if (e >= n_edges) return;
    int row = __ldg(&edge_index[e]);
    int col = __ldg(&edge_index[n_edges + e]);
    float a = (1.0f - __ldg(&eps[0])) * tanhf(g_s1[row] + g_s2[col] + __ldg(&att_b[0]));
    unsigned p = atomicAdd(&g_cur[col], 1u);
    g_pairs[p] = make_int2(row, __float_as_int(a));
}

// ---------------------------------------------------------------------------
// K5: gather. One warp per destination node; re-zeroes g_deg for next call.
// out[c] = eps*x[c] + sum_e alpha_e * x[row_e]
// ---------------------------------------------------------------------------
__global__ void gather_kernel(const float* __restrict__ x,
                              const float* __restrict__ eps,
                              float* __restrict__ out,
                              int n_nodes) {
    int gtid = blockIdx.x * blockDim.x + threadIdx.x;
    int node = gtid >> 5;
    int lane = threadIdx.x & 31;
    if (node >= n_nodes) return;

    if (lane == 0) g_deg[node] = 0u;   // leave histogram clean for next call

    int beg = g_off[node];
    int end = g_off[node + 1];
    const float4* x4 = reinterpret_cast<const float4*>(x);

    float4 acc = make_float4(0.f, 0.f, 0.f, 0.f);

    int i = beg;
    for (; i + 4 <= end; i += 4) {
        int2 p0 = __ldg(&g_pairs[i]);
        int2 p1 = __ldg(&g_pairs[i + 1]);
        int2 p2 = __ldg(&g_pairs[i + 2]);
        int2 p3 = __ldg(&g_pairs[i + 3]);
        float4 v0 = __ldg(&x4[(size_t)p0.x * 32 + lane]);
        float4 v1 = __ldg(&x4[(size_t)p1.x * 32 + lane]);
        float4 v2 = __ldg(&x4[(size_t)p2.x * 32 + lane]);
        float4 v3 = __ldg(&x4[(size_t)p3.x * 32 + lane]);
        float a0 = __int_as_float(p0.y), a1 = __int_as_float(p1.y);
        float a2 = __int_as_float(p2.y), a3 = __int_as_float(p3.y);
        acc.x += a0 * v0.x + a1 * v1.x + a2 * v2.x + a3 * v3.x;
        acc.y += a0 * v0.y + a1 * v1.y + a2 * v2.y + a3 * v3.y;
        acc.z += a0 * v0.z + a1 * v1.z + a2 * v2.z + a3 * v3.z;
        acc.w += a0 * v0.w + a1 * v1.w + a2 * v2.w + a3 * v3.w;
    }
    for (; i < end; ++i) {
        int2 p = __ldg(&g_pairs[i]);
        float4 v = __ldg(&x4[(size_t)p.x * 32 + lane]);
        float a = __int_as_float(p.y);
        acc.x += a * v.x; acc.y += a * v.y; acc.z += a * v.z; acc.w += a * v.w;
    }

    float e = __ldg(&eps[0]);
    float4 xc = __ldg(&x4[(size_t)node * 32 + lane]);
    float4 o;
    o.x = e * xc.x + acc.x;
    o.y = e * xc.y + acc.y;
    o.z = e * xc.z + acc.z;
    o.w = e * xc.w + acc.w;
    reinterpret_cast<float4*>(out)[(size_t)node * 32 + lane] = o;
}

// ---------------------------------------------------------------------------
// Launch
// ---------------------------------------------------------------------------
extern "C" void kernel_launch(void* const* d_in, const int* in_sizes, int n_in,
                              void* d_out, int out_size) {
    const float* x     = (const float*)d_in[0];   // [N, 128] f32
    const int*   ei    = (const int*)d_in[1];     // [2, E] int32
    const float* att_w = (const float*)d_in[2];   // [1, 256]
    const float* att_b = (const float*)d_in[3];   // [1]
    const float* eps   = (const float*)d_in[4];   // [1]
    float*       out   = (float*)d_out;           // [N, 128]

    const int n_nodes = in_sizes[0] / HIDDEN;
    const int n_edges = in_sizes[1] / 2;
    const int nb_scan = (n_nodes + SCAN_BLK - 1) / SCAN_BLK;

    // K1: fused dots (4 nodes/warp) + histogram
    {
        int warps  = (n_nodes + 3) / 4;
        int blocks = (warps * 32 + 255) / 256;   // 1250 for N=40000
        dots_hist_kernel<<<blocks, 256>>>(x, att_w, ei, n_nodes, n_edges);
    }

    // K2+K3: two-kernel exclusive scan
    scan1_kernel<<<nb_scan, SCAN_BLK>>>(n_nodes);
    scan_fin_kernel<<<nb_scan, SCAN_BLK>>>(n_nodes, n_edges);

    // K4: alpha + scatter into CSR bins
    alpha_scatter_kernel<<<(n_edges + 255) / 256, 256>>>(ei, att_b, eps, n_edges);

    // K5: gather (one warp/node), init + deg-reset fused
    {
        int blocks = (n_nodes * 32 + 255) / 256;
        gather_kernel<<<blocks, 256>>>(x, eps, out, n_nodes);
    }
}